// round 1
// baseline (speedup 1.0000x reference)
#include <cuda_runtime.h>
#include <math.h>

#define B_ROWS   8192
#define D_INF    2048
#define D_BOT    1024
#define C_CLS    1000
#define SHARE    500
#define NEG_FILL (-1e9f)
#define INV_TEMP 20.0f
#define EPSN     1e-12f

// ---------------- scratch (static device globals; no allocation) ----------------
__device__ __align__(128) float g_sm1[(size_t)B_ROWS * C_CLS];       // masked softmax probs
__device__ __align__(128) float g_centroidT[(size_t)D_BOT * C_CLS];  // centroid^T [D_BOT, C]
__device__ __align__(128) float g_inv_norm[B_ROWS];                  // 1/max(||row||,eps)

// =====================================================================
// Tiled fp32 GEMM:  C[M,N] = A[M,K] * B[N,K]^T  (+ epilogue)
//   MODE 0: C += bias[n]            (aux = bias, len N)
//   MODE 1: plain
//   MODE 2: C += aux[m*N + n]       (aux = residual matrix, same shape)
//   MODE 3: C *= aux[m] * INV_TEMP  (aux = per-row scale, len M)
// Requirements: M % 128 == 0. N, K arbitrary (guarded). Rows of A/B must be
// 16B-aligned when (K*4)%16==0 and base 16B-aligned — true for all our calls.
// =====================================================================
template <int MODE>
__global__ void __launch_bounds__(256)
gemm_nt(const float* __restrict__ A, const float* __restrict__ Bm,
        float* __restrict__ Cm, int M, int N, int K,
        const float* __restrict__ aux)
{
    constexpr int BM = 128, BN = 128, BK = 16;
    __shared__ float As[BK][BM];
    __shared__ float Bs[BK][BN];

    const int tid = threadIdx.x;
    const int bm = blockIdx.y * BM;
    const int bn = blockIdx.x * BN;

    // loader mapping: 256 threads, each loads 2x float4 per operand tile
    const int lr = tid >> 2;          // 0..63
    const int lc = (tid & 3) * 4;     // 0,4,8,12

    // compute mapping: 16x16 thread grid, 8x8 micro-tile each
    const int ty = tid >> 4;
    const int tx = tid & 15;
    const int tm = ty * 8;
    const int tn = tx * 8;

    float acc[8][8];
#pragma unroll
    for (int i = 0; i < 8; i++)
#pragma unroll
        for (int j = 0; j < 8; j++) acc[i][j] = 0.f;

    for (int k0 = 0; k0 < K; k0 += BK) {
        // ---- load A tile (BM x BK), store transposed As[k][m] ----
#pragma unroll
        for (int h = 0; h < 2; h++) {
            const int row = lr + 64 * h;
            const int grow = bm + row;            // grow < M always (M%128==0)
            float4 v = make_float4(0.f, 0.f, 0.f, 0.f);
            if (k0 + lc + 3 < K) {
                v = *reinterpret_cast<const float4*>(A + (size_t)grow * K + k0 + lc);
            } else if (k0 + lc < K) {
                const float* p = A + (size_t)grow * K + k0 + lc;
                float t0 = p[0];
                float t1 = (k0 + lc + 1 < K) ? p[1] : 0.f;
                float t2 = (k0 + lc + 2 < K) ? p[2] : 0.f;
                v = make_float4(t0, t1, t2, 0.f);
            }
            As[lc + 0][row] = v.x;
            As[lc + 1][row] = v.y;
            As[lc + 2][row] = v.z;
            As[lc + 3][row] = v.w;
        }
        // ---- load B tile (BN x BK), store transposed Bs[k][n] ----
#pragma unroll
        for (int h = 0; h < 2; h++) {
            const int row = lr + 64 * h;
            const int grow = bn + row;
            float4 v = make_float4(0.f, 0.f, 0.f, 0.f);
            if (grow < N) {
                if (k0 + lc + 3 < K) {
                    v = *reinterpret_cast<const float4*>(Bm + (size_t)grow * K + k0 + lc);
                } else if (k0 + lc < K) {
                    const float* p = Bm + (size_t)grow * K + k0 + lc;
                    float t0 = p[0];
                    float t1 = (k0 + lc + 1 < K) ? p[1] : 0.f;
                    float t2 = (k0 + lc + 2 < K) ? p[2] : 0.f;
                    v = make_float4(t0, t1, t2, 0.f);
                }
            }
            Bs[lc + 0][row] = v.x;
            Bs[lc + 1][row] = v.y;
            Bs[lc + 2][row] = v.z;
            Bs[lc + 3][row] = v.w;
        }
        __syncthreads();

#pragma unroll
        for (int k = 0; k < BK; k++) {
            float a[8], b[8];
            *reinterpret_cast<float4*>(&a[0]) = *reinterpret_cast<const float4*>(&As[k][tm]);
            *reinterpret_cast<float4*>(&a[4]) = *reinterpret_cast<const float4*>(&As[k][tm + 4]);
            *reinterpret_cast<float4*>(&b[0]) = *reinterpret_cast<const float4*>(&Bs[k][tn]);
            *reinterpret_cast<float4*>(&b[4]) = *reinterpret_cast<const float4*>(&Bs[k][tn + 4]);
#pragma unroll
            for (int i = 0; i < 8; i++)
#pragma unroll
                for (int j = 0; j < 8; j++)
                    acc[i][j] = fmaf(a[i], b[j], acc[i][j]);
        }
        __syncthreads();
    }

    // ---- epilogue + store ----
#pragma unroll
    for (int i = 0; i < 8; i++) {
        const int m = bm + tm + i;
#pragma unroll
        for (int j = 0; j < 8; j++) {
            const int n = bn + tn + j;
            if (n < N) {
                float c = acc[i][j];
                if (MODE == 0) c += aux[n];
                else if (MODE == 2) c += aux[(size_t)m * N + n];
                else if (MODE == 3) c *= aux[m] * INV_TEMP;
                Cm[(size_t)m * N + n] = c;
            }
        }
    }
}

// ============ centroid transpose: [C, D_BOT] -> g_centroidT [D_BOT, C] ============
__global__ void transpose_centroid(const float* __restrict__ src)
{
    __shared__ float tile[32][33];
    const int bx = blockIdx.x * 32;  // along D_BOT
    const int by = blockIdx.y * 32;  // along C
    const int x = bx + threadIdx.x;  // d index
#pragma unroll
    for (int i = 0; i < 32; i += 8) {
        const int c = by + threadIdx.y + i;
        tile[threadIdx.y + i][threadIdx.x] =
            (c < C_CLS && x < D_BOT) ? src[(size_t)c * D_BOT + x] : 0.f;
    }
    __syncthreads();
    const int c2 = by + threadIdx.x;
#pragma unroll
    for (int i = 0; i < 32; i += 8) {
        const int d2 = bx + threadIdx.y + i;
        if (d2 < D_BOT && c2 < C_CLS)
            g_centroidT[(size_t)d2 * C_CLS + c2] = tile[threadIdx.x][threadIdx.y + i];
    }
}

// ============ masked softmax over outputs1 rows -> g_sm1 ============
__global__ void __launch_bounds__(256)
mask_softmax(const float* __restrict__ logits)
{
    const int row = blockIdx.x;
    const float* x = logits + (size_t)row * C_CLS;
    const int t = threadIdx.x;

    float v[4];
    float lmax = -INFINITY;
    int limax = C_CLS;
#pragma unroll
    for (int i = 0; i < 4; i++) {
        const int j = t + i * 256;
        const float val = (j < C_CLS) ? x[j] : -INFINITY;
        v[i] = val;
        if (val > lmax) { lmax = val; limax = j; }  // strided j increasing -> keeps first
    }

    __shared__ float smax[256];
    __shared__ int   simax[256];
    smax[t] = lmax; simax[t] = limax;
    __syncthreads();
#pragma unroll
    for (int s = 128; s > 0; s >>= 1) {
        if (t < s) {
            const float o = smax[t + s]; const int oi = simax[t + s];
            if (o > smax[t] || (o == smax[t] && oi < simax[t])) { smax[t] = o; simax[t] = oi; }
        }
        __syncthreads();
    }
    const int predict = simax[0];
    const float rowmax = smax[0];
    const bool priv = (predict >= SHARE);

    float e[4];
    float lsum = 0.f;
#pragma unroll
    for (int i = 0; i < 4; i++) {
        const int j = t + i * 256;
        float ee = 0.f;
        if (j < C_CLS) {
            bool mask;
            if (j == predict) mask = false;
            else if (priv)    mask = true;
            else              mask = (j < SHARE);
            const float val = mask ? NEG_FILL : v[i];
            ee = expf(val - rowmax);   // NEG_FILL path underflows to exact 0
            lsum += ee;
        }
        e[i] = ee;
    }

    __shared__ float ssum[256];
    ssum[t] = lsum;
    __syncthreads();
#pragma unroll
    for (int s = 128; s > 0; s >>= 1) {
        if (t < s) ssum[t] += ssum[t + s];
        __syncthreads();
    }
    const float inv = 1.f / ssum[0];

    float* o = g_sm1 + (size_t)row * C_CLS;
#pragma unroll
    for (int i = 0; i < 4; i++) {
        const int j = t + i * 256;
        if (j < C_CLS) o[j] = e[i] * inv;
    }
}

// ============ per-row inverse L2 norm of features_aug ============
__global__ void __launch_bounds__(256)
row_inv_norm(const float* __restrict__ x)
{
    const int row = blockIdx.x;
    const int t = threadIdx.x;
    const float4 v = reinterpret_cast<const float4*>(x + (size_t)row * D_BOT)[t];
    float s = v.x * v.x + v.y * v.y + v.z * v.z + v.w * v.w;
    __shared__ float sh[256];
    sh[t] = s;
    __syncthreads();
#pragma unroll
    for (int k = 128; k > 0; k >>= 1) {
        if (t < k) sh[t] += sh[t + k];
        __syncthreads();
    }
    if (t == 0) g_inv_norm[row] = 1.f / fmaxf(sqrtf(sh[0]), EPSN);
}

// ============ plain row softmax (outputs2 -> softmax_outputs) ============
__global__ void __launch_bounds__(256)
softmax_rows(const float* __restrict__ in, float* __restrict__ outp)
{
    const int row = blockIdx.x;
    const float* x = in + (size_t)row * C_CLS;
    const int t = threadIdx.x;

    float v[4];
    float lmax = -INFINITY;
#pragma unroll
    for (int i = 0; i < 4; i++) {
        const int j = t + i * 256;
        v[i] = (j < C_CLS) ? x[j] : -INFINITY;
        lmax = fmaxf(lmax, v[i]);
    }
    __shared__ float sh[256];
    sh[t] = lmax;
    __syncthreads();
#pragma unroll
    for (int s = 128; s > 0; s >>= 1) {
        if (t < s) sh[t] = fmaxf(sh[t], sh[t + s]);
        __syncthreads();
    }
    const float rowmax = sh[0];
    __syncthreads();

    float e[4];
    float lsum = 0.f;
#pragma unroll
    for (int i = 0; i < 4; i++) {
        const int j = t + i * 256;
        float ee = 0.f;
        if (j < C_CLS) { ee = expf(v[i] - rowmax); lsum += ee; }
        e[i] = ee;
    }
    sh[t] = lsum;
    __syncthreads();
#pragma unroll
    for (int s = 128; s > 0; s >>= 1) {
        if (t < s) sh[t] += sh[t + s];
        __syncthreads();
    }
    const float inv = 1.f / sh[0];

    float* o = outp + (size_t)row * C_CLS;
#pragma unroll
    for (int i = 0; i < 4; i++) {
        const int j = t + i * 256;
        if (j < C_CLS) o[j] = e[i] * inv;
    }
}

// =====================================================================
extern "C" void kernel_launch(void* const* d_in, const int* in_sizes, int n_in,
                              void* d_out, int out_size)
{
    const float* features = (const float*)d_in[0];  // [8192, 2048]
    const float* W_b      = (const float*)d_in[1];  // [1024, 2048]
    const float* b_b      = (const float*)d_in[2];  // [1024]
    const float* W1       = (const float*)d_in[3];  // [1000, 1024]
    const float* W2       = (const float*)d_in[4];  // [1000, 1024]
    const float* centroid = (const float*)d_in[5];  // [1000, 1024]

    float* out = (float*)d_out;
    float* feats        = out;                                        // [8192,1024]
    float* features_aug = feats + (size_t)B_ROWS * D_BOT;             // [8192,1024]
    float* outputs1     = features_aug + (size_t)B_ROWS * D_BOT;      // [8192,1000]
    float* outputs2     = outputs1 + (size_t)B_ROWS * C_CLS;          // [8192,1000]
    float* softmax_out  = outputs2 + (size_t)B_ROWS * C_CLS;          // [8192,1000]

    float* sm1p = nullptr;
    float* cTp = nullptr;
    cudaGetSymbolAddress((void**)&sm1p, g_sm1);
    cudaGetSymbolAddress((void**)&cTp, g_centroidT);
    float* invnp = nullptr;
    cudaGetSymbolAddress((void**)&invnp, g_inv_norm);

    const dim3 blk(256);
    const dim3 grid_b1024((D_BOT + 127) / 128, B_ROWS / 128);
    const dim3 grid_c((C_CLS + 127) / 128, B_ROWS / 128);

    // centroid^T (independent; kick off first)
    transpose_centroid<<<dim3(D_BOT / 32, (C_CLS + 31) / 32), dim3(32, 8)>>>(centroid);

    // GEMM1: feats = features @ W_b^T + b_b
    gemm_nt<0><<<grid_b1024, blk>>>(features, W_b, feats, B_ROWS, D_BOT, D_INF, b_b);

    // GEMM2: outputs1 = feats @ W1^T
    gemm_nt<1><<<grid_c, blk>>>(feats, W1, outputs1, B_ROWS, C_CLS, D_BOT, nullptr);

    // masked softmax -> g_sm1
    mask_softmax<<<B_ROWS, blk>>>(outputs1);

    // GEMM3: features_aug = sm1 @ centroid + feats
    gemm_nt<2><<<grid_b1024, blk>>>(sm1p, cTp, features_aug, B_ROWS, D_BOT, C_CLS, feats);

    // per-row inverse norm
    row_inv_norm<<<B_ROWS, blk>>>(features_aug);

    // GEMM4: outputs2 = (features_aug * inv_norm[m]) @ W2^T / TEMP
    gemm_nt<3><<<grid_c, blk>>>(features_aug, W2, outputs2, B_ROWS, C_CLS, D_BOT, invnp);

    // final softmax
    softmax_rows<<<B_ROWS, blk>>>(outputs2, softmax_out);
}

// round 2
// speedup vs baseline: 1.0051x; 1.0051x over previous
#include <cuda_runtime.h>
#include <math.h>

#define B_ROWS   8192
#define D_INF    2048
#define D_BOT    1024
#define C_CLS    1000
#define SHARE    500
#define NEG_FILL (-1e9f)
#define INV_TEMP 20.0f
#define EPSN     1e-12f

// ---------------- scratch (static device globals; no allocation) ----------------
__device__ __align__(128) float g_sm1[(size_t)B_ROWS * C_CLS];       // masked softmax probs
__device__ __align__(128) float g_centroidT[(size_t)D_BOT * C_CLS];  // centroid^T [D_BOT, C]
__device__ __align__(128) float g_inv_norm[B_ROWS];                  // 1/max(||row||,eps)

// =====================================================================
// Tiled fp32 GEMM:  C[M,N] = A[M,K] * B[N,K]^T  (+ epilogue)
//   MODE 0: C += bias[n]            (aux = bias, len N)
//   MODE 1: plain
//   MODE 2: C += aux[m*N + n]       (aux = residual matrix, same shape)
//   MODE 3: C *= aux[m] * INV_TEMP  (aux = per-row scale, len M)
// Requirements: M % 128 == 0. N, K arbitrary (guarded). Rows of A/B must be
// 16B-aligned when (K*4)%16==0 and base 16B-aligned — true for all our calls.
// =====================================================================
template <int MODE>
__global__ void __launch_bounds__(256)
gemm_nt(const float* __restrict__ A, const float* __restrict__ Bm,
        float* __restrict__ Cm, int M, int N, int K,
        const float* __restrict__ aux)
{
    constexpr int BM = 128, BN = 128, BK = 16;
    __shared__ float As[BK][BM];
    __shared__ float Bs[BK][BN];

    const int tid = threadIdx.x;
    const int bm = blockIdx.y * BM;
    const int bn = blockIdx.x * BN;

    // loader mapping: 256 threads, each loads 2x float4 per operand tile
    const int lr = tid >> 2;          // 0..63
    const int lc = (tid & 3) * 4;     // 0,4,8,12

    // compute mapping: 16x16 thread grid, 8x8 micro-tile each
    const int ty = tid >> 4;
    const int tx = tid & 15;
    const int tm = ty * 8;
    const int tn = tx * 8;

    float acc[8][8];
#pragma unroll
    for (int i = 0; i < 8; i++)
#pragma unroll
        for (int j = 0; j < 8; j++) acc[i][j] = 0.f;

    for (int k0 = 0; k0 < K; k0 += BK) {
        // ---- load A tile (BM x BK), store transposed As[k][m] ----
#pragma unroll
        for (int h = 0; h < 2; h++) {
            const int row = lr + 64 * h;
            const int grow = bm + row;            // grow < M always (M%128==0)
            float4 v = make_float4(0.f, 0.f, 0.f, 0.f);
            if (k0 + lc + 3 < K) {
                v = *reinterpret_cast<const float4*>(A + (size_t)grow * K + k0 + lc);
            } else if (k0 + lc < K) {
                const float* p = A + (size_t)grow * K + k0 + lc;
                float t0 = p[0];
                float t1 = (k0 + lc + 1 < K) ? p[1] : 0.f;
                float t2 = (k0 + lc + 2 < K) ? p[2] : 0.f;
                v = make_float4(t0, t1, t2, 0.f);
            }
            As[lc + 0][row] = v.x;
            As[lc + 1][row] = v.y;
            As[lc + 2][row] = v.z;
            As[lc + 3][row] = v.w;
        }
        // ---- load B tile (BN x BK), store transposed Bs[k][n] ----
#pragma unroll
        for (int h = 0; h < 2; h++) {
            const int row = lr + 64 * h;
            const int grow = bn + row;
            float4 v = make_float4(0.f, 0.f, 0.f, 0.f);
            if (grow < N) {
                if (k0 + lc + 3 < K) {
                    v = *reinterpret_cast<const float4*>(Bm + (size_t)grow * K + k0 + lc);
                } else if (k0 + lc < K) {
                    const float* p = Bm + (size_t)grow * K + k0 + lc;
                    float t0 = p[0];
                    float t1 = (k0 + lc + 1 < K) ? p[1] : 0.f;
                    float t2 = (k0 + lc + 2 < K) ? p[2] : 0.f;
                    v = make_float4(t0, t1, t2, 0.f);
                }
            }
            Bs[lc + 0][row] = v.x;
            Bs[lc + 1][row] = v.y;
            Bs[lc + 2][row] = v.z;
            Bs[lc + 3][row] = v.w;
        }
        __syncthreads();

#pragma unroll
        for (int k = 0; k < BK; k++) {
            float a[8], b[8];
            *reinterpret_cast<float4*>(&a[0]) = *reinterpret_cast<const float4*>(&As[k][tm]);
            *reinterpret_cast<float4*>(&a[4]) = *reinterpret_cast<const float4*>(&As[k][tm + 4]);
            *reinterpret_cast<float4*>(&b[0]) = *reinterpret_cast<const float4*>(&Bs[k][tn]);
            *reinterpret_cast<float4*>(&b[4]) = *reinterpret_cast<const float4*>(&Bs[k][tn + 4]);
#pragma unroll
            for (int i = 0; i < 8; i++)
#pragma unroll
                for (int j = 0; j < 8; j++)
                    acc[i][j] = fmaf(a[i], b[j], acc[i][j]);
        }
        __syncthreads();
    }

    // ---- epilogue + store ----
#pragma unroll
    for (int i = 0; i < 8; i++) {
        const int m = bm + tm + i;
#pragma unroll
        for (int j = 0; j < 8; j++) {
            const int n = bn + tn + j;
            if (n < N) {
                float c = acc[i][j];
                if (MODE == 0) c += aux[n];
                else if (MODE == 2) c += aux[(size_t)m * N + n];
                else if (MODE == 3) c *= aux[m] * INV_TEMP;
                Cm[(size_t)m * N + n] = c;
            }
        }
    }
}

// ============ centroid transpose: [C, D_BOT] -> g_centroidT [D_BOT, C] ============
__global__ void transpose_centroid(const float* __restrict__ src)
{
    __shared__ float tile[32][33];
    const int bx = blockIdx.x * 32;  // along D_BOT
    const int by = blockIdx.y * 32;  // along C
    const int x = bx + threadIdx.x;  // d index
#pragma unroll
    for (int i = 0; i < 32; i += 8) {
        const int c = by + threadIdx.y + i;
        tile[threadIdx.y + i][threadIdx.x] =
            (c < C_CLS && x < D_BOT) ? src[(size_t)c * D_BOT + x] : 0.f;
    }
    __syncthreads();
    const int c2 = by + threadIdx.x;
#pragma unroll
    for (int i = 0; i < 32; i += 8) {
        const int d2 = bx + threadIdx.y + i;
        if (d2 < D_BOT && c2 < C_CLS)
            g_centroidT[(size_t)d2 * C_CLS + c2] = tile[threadIdx.x][threadIdx.y + i];
    }
}

// ============ masked softmax over outputs1 rows -> g_sm1 ============
__global__ void __launch_bounds__(256)
mask_softmax(const float* __restrict__ logits)
{
    const int row = blockIdx.x;
    const float* x = logits + (size_t)row * C_CLS;
    const int t = threadIdx.x;

    float v[4];
    float lmax = -INFINITY;
    int limax = C_CLS;
#pragma unroll
    for (int i = 0; i < 4; i++) {
        const int j = t + i * 256;
        const float val = (j < C_CLS) ? x[j] : -INFINITY;
        v[i] = val;
        if (val > lmax) { lmax = val; limax = j; }  // strided j increasing -> keeps first
    }

    __shared__ float smax[256];
    __shared__ int   simax[256];
    smax[t] = lmax; simax[t] = limax;
    __syncthreads();
#pragma unroll
    for (int s = 128; s > 0; s >>= 1) {
        if (t < s) {
            const float o = smax[t + s]; const int oi = simax[t + s];
            if (o > smax[t] || (o == smax[t] && oi < simax[t])) { smax[t] = o; simax[t] = oi; }
        }
        __syncthreads();
    }
    const int predict = simax[0];
    const float rowmax = smax[0];
    const bool priv = (predict >= SHARE);

    float e[4];
    float lsum = 0.f;
#pragma unroll
    for (int i = 0; i < 4; i++) {
        const int j = t + i * 256;
        float ee = 0.f;
        if (j < C_CLS) {
            bool mask;
            if (j == predict) mask = false;
            else if (priv)    mask = true;
            else              mask = (j < SHARE);
            const float val = mask ? NEG_FILL : v[i];
            ee = expf(val - rowmax);   // NEG_FILL path underflows to exact 0
            lsum += ee;
        }
        e[i] = ee;
    }

    __shared__ float ssum[256];
    ssum[t] = lsum;
    __syncthreads();
#pragma unroll
    for (int s = 128; s > 0; s >>= 1) {
        if (t < s) ssum[t] += ssum[t + s];
        __syncthreads();
    }
    const float inv = 1.f / ssum[0];

    float* o = g_sm1 + (size_t)row * C_CLS;
#pragma unroll
    for (int i = 0; i < 4; i++) {
        const int j = t + i * 256;
        if (j < C_CLS) o[j] = e[i] * inv;
    }
}

// ============ per-row inverse L2 norm of features_aug ============
__global__ void __launch_bounds__(256)
row_inv_norm(const float* __restrict__ x)
{
    const int row = blockIdx.x;
    const int t = threadIdx.x;
    const float4 v = reinterpret_cast<const float4*>(x + (size_t)row * D_BOT)[t];
    float s = v.x * v.x + v.y * v.y + v.z * v.z + v.w * v.w;
    __shared__ float sh[256];
    sh[t] = s;
    __syncthreads();
#pragma unroll
    for (int k = 128; k > 0; k >>= 1) {
        if (t < k) sh[t] += sh[t + k];
        __syncthreads();
    }
    if (t == 0) g_inv_norm[row] = 1.f / fmaxf(sqrtf(sh[0]), EPSN);
}

// ============ plain row softmax (outputs2 -> softmax_outputs) ============
__global__ void __launch_bounds__(256)
softmax_rows(const float* __restrict__ in, float* __restrict__ outp)
{
    const int row = blockIdx.x;
    const float* x = in + (size_t)row * C_CLS;
    const int t = threadIdx.x;

    float v[4];
    float lmax = -INFINITY;
#pragma unroll
    for (int i = 0; i < 4; i++) {
        const int j = t + i * 256;
        v[i] = (j < C_CLS) ? x[j] : -INFINITY;
        lmax = fmaxf(lmax, v[i]);
    }
    __shared__ float sh[256];
    sh[t] = lmax;
    __syncthreads();
#pragma unroll
    for (int s = 128; s > 0; s >>= 1) {
        if (t < s) sh[t] = fmaxf(sh[t], sh[t + s]);
        __syncthreads();
    }
    const float rowmax = sh[0];
    __syncthreads();

    float e[4];
    float lsum = 0.f;
#pragma unroll
    for (int i = 0; i < 4; i++) {
        const int j = t + i * 256;
        float ee = 0.f;
        if (j < C_CLS) { ee = expf(v[i] - rowmax); lsum += ee; }
        e[i] = ee;
    }
    sh[t] = lsum;
    __syncthreads();
#pragma unroll
    for (int s = 128; s > 0; s >>= 1) {
        if (t < s) sh[t] += sh[t + s];
        __syncthreads();
    }
    const float inv = 1.f / sh[0];

    float* o = outp + (size_t)row * C_CLS;
#pragma unroll
    for (int i = 0; i < 4; i++) {
        const int j = t + i * 256;
        if (j < C_CLS) o[j] = e[i] * inv;
    }
}

// =====================================================================
extern "C" void kernel_launch(void* const* d_in, const int* in_sizes, int n_in,
                              void* d_out, int out_size)
{
    const float* features = (const float*)d_in[0];  // [8192, 2048]
    const float* W_b      = (const float*)d_in[1];  // [1024, 2048]
    const float* b_b      = (const float*)d_in[2];  // [1024]
    const float* W1       = (const float*)d_in[3];  // [1000, 1024]
    const float* W2       = (const float*)d_in[4];  // [1000, 1024]
    const float* centroid = (const float*)d_in[5];  // [1000, 1024]

    float* out = (float*)d_out;
    float* feats        = out;                                        // [8192,1024]
    float* features_aug = feats + (size_t)B_ROWS * D_BOT;             // [8192,1024]
    float* outputs1     = features_aug + (size_t)B_ROWS * D_BOT;      // [8192,1000]
    float* outputs2     = outputs1 + (size_t)B_ROWS * C_CLS;          // [8192,1000]
    float* softmax_out  = outputs2 + (size_t)B_ROWS * C_CLS;          // [8192,1000]

    float* sm1p = nullptr;
    float* cTp = nullptr;
    cudaGetSymbolAddress((void**)&sm1p, g_sm1);
    cudaGetSymbolAddress((void**)&cTp, g_centroidT);
    float* invnp = nullptr;
    cudaGetSymbolAddress((void**)&invnp, g_inv_norm);

    const dim3 blk(256);
    const dim3 grid_b1024((D_BOT + 127) / 128, B_ROWS / 128);
    const dim3 grid_c((C_CLS + 127) / 128, B_ROWS / 128);

    // centroid^T (independent; kick off first)
    transpose_centroid<<<dim3(D_BOT / 32, (C_CLS + 31) / 32), dim3(32, 8)>>>(centroid);

    // GEMM1: feats = features @ W_b^T + b_b
    gemm_nt<0><<<grid_b1024, blk>>>(features, W_b, feats, B_ROWS, D_BOT, D_INF, b_b);

    // GEMM2: outputs1 = feats @ W1^T
    gemm_nt<1><<<grid_c, blk>>>(feats, W1, outputs1, B_ROWS, C_CLS, D_BOT, nullptr);

    // masked softmax -> g_sm1
    mask_softmax<<<B_ROWS, blk>>>(outputs1);

    // GEMM3: features_aug = sm1 @ centroid + feats
    gemm_nt<2><<<grid_b1024, blk>>>(sm1p, cTp, features_aug, B_ROWS, D_BOT, C_CLS, feats);

    // per-row inverse norm
    row_inv_norm<<<B_ROWS, blk>>>(features_aug);

    // GEMM4: outputs2 = (features_aug * inv_norm[m]) @ W2^T / TEMP
    gemm_nt<3><<<grid_c, blk>>>(features_aug, W2, outputs2, B_ROWS, C_CLS, D_BOT, invnp);

    // final softmax
    softmax_rows<<<B_ROWS, blk>>>(outputs2, softmax_out);
}

// round 4
// speedup vs baseline: 1.8665x; 1.8570x over previous
#include <cuda_runtime.h>
#include <cuda_bf16.h>
#include <math.h>
#include <stdint.h>

#define B_ROWS   8192
#define D_INF    2048
#define D_BOT    1024
#define C_CLS    1000
#define C_PAD    1024
#define SHARE    500
#define NEG_FILL (-1e9f)
#define INV_TEMP 20.0f
#define EPSN     1e-12f

// ===================== scratch (static device globals) =====================
__device__ __align__(1024) __nv_bfloat16 g_feat3 [3][(size_t)B_ROWS * D_INF];
__device__ __align__(1024) __nv_bfloat16 g_Wb3   [3][(size_t)D_BOT  * D_INF];
__device__ __align__(1024) __nv_bfloat16 g_feats3[3][(size_t)B_ROWS * D_BOT];
__device__ __align__(1024) __nv_bfloat16 g_W1s   [3][(size_t)C_PAD  * D_BOT];
__device__ __align__(1024) __nv_bfloat16 g_sm1s  [2][(size_t)B_ROWS * C_PAD];
__device__ __align__(1024) __nv_bfloat16 g_cTs   [2][(size_t)D_BOT  * C_PAD];
__device__ __align__(1024) __nv_bfloat16 g_faug2 [2][(size_t)B_ROWS * D_BOT];
__device__ __align__(1024) __nv_bfloat16 g_W2s   [2][(size_t)C_PAD  * D_BOT];
__device__ float g_inv[B_ROWS];

// ===================== helpers =====================
__device__ __forceinline__ uint32_t smem_u32(const void* p) {
    return (uint32_t)__cvta_generic_to_shared(p);
}
__device__ __forceinline__ void cp16(uint32_t sdst, const void* gsrc) {
    asm volatile("cp.async.cg.shared.global [%0], [%1], 16;" :: "r"(sdst), "l"(gsrc));
}
#define CP_COMMIT() asm volatile("cp.async.commit_group;" ::: "memory")
#define CP_WAIT1()  asm volatile("cp.async.wait_group 1;" ::: "memory")

#define LDSM_X4(r0, r1, r2, r3, addr) \
    asm volatile("ldmatrix.sync.aligned.m8n8.x4.shared.b16 {%0,%1,%2,%3}, [%4];" \
        : "=r"(r0), "=r"(r1), "=r"(r2), "=r"(r3) : "r"(addr))
#define LDSM_X2(r0, r1, addr) \
    asm volatile("ldmatrix.sync.aligned.m8n8.x2.shared.b16 {%0,%1}, [%2];" \
        : "=r"(r0), "=r"(r1) : "r"(addr))

__device__ __forceinline__ void mma_16816(float* c, const uint32_t* a, const uint32_t* b) {
    asm volatile(
        "mma.sync.aligned.m16n8k16.row.col.f32.bf16.bf16.f32 "
        "{%0,%1,%2,%3}, {%4,%5,%6,%7}, {%8,%9}, {%0,%1,%2,%3};"
        : "+f"(c[0]), "+f"(c[1]), "+f"(c[2]), "+f"(c[3])
        : "r"(a[0]), "r"(a[1]), "r"(a[2]), "r"(a[3]), "r"(b[0]), "r"(b[1]));
}

__device__ __forceinline__ void split2f(float x, __nv_bfloat16& h, __nv_bfloat16& m) {
    h = __float2bfloat16(x);
    m = __float2bfloat16(x - __bfloat162float(h));
}
__device__ __forceinline__ __nv_bfloat16 third_comp(float x, __nv_bfloat16 h, __nv_bfloat16 m) {
    return __float2bfloat16((x - __bfloat162float(h)) - __bfloat162float(m));
}

// ===================== bf16 split GEMM via mma.sync =====================
// C[8192, Nout](+epilogue) = sum_terms A_c[8192,K] @ B_c[1024,K]^T ; block tile 128x128, BK=32
//  MODE 0: +bias[n], store stride D_BOT
//  MODE 1: plain, store stride Nout, guard n<Nout
//  MODE 2: +aux[m*D_BOT+n], store stride D_BOT
//  MODE 3: *INV_TEMP, store stride Nout, guard
// smem tile: 128 rows x (64B data + 16B pad) = 10240 B. Stage = 2*NC tiles.
template <int NC, int MODE>
__global__ void __launch_bounds__(256)
gemm_mma(const __nv_bfloat16* __restrict__ A, size_t sA,
         const __nv_bfloat16* __restrict__ B, size_t sB,
         float* __restrict__ C, int K, int Nout,
         const float* __restrict__ aux)
{
    extern __shared__ __align__(128) char smem[];
    const uint32_t sb = smem_u32(smem);
    const int tid = threadIdx.x;
    const int wid = tid >> 5;
    const int lane = tid & 31;
    const int bm = blockIdx.y * 128;
    const int bn = blockIdx.x * 128;

    constexpr int TILEB = 128 * 80;            // 10240 B per operand tile
    constexpr int STAGE = 2 * NC * TILEB;
    constexpr int NT = (NC == 3) ? 6 : 3;

    const int wm = (wid >> 2) * 64;            // warp m-offset (0/64)
    const int wn = (wid & 3) * 32;             // warp n-offset (0/32/64/96)

    // ldmatrix per-lane intra-tile offsets
    const uint32_t a_lo = (uint32_t)((lane & 15) * 80 + (lane >> 4) * 16);
    const uint32_t b_lo = (uint32_t)((lane & 7) * 80 + ((lane >> 3) & 1) * 16);

    // loader mapping: segment index -> (row, 16B seg)
    const int l_row0 = tid >> 2;          // +64 for second
    const int l_seg = tid & 3;

    float acc[4][4][4];
#pragma unroll
    for (int i = 0; i < 4; i++)
#pragma unroll
        for (int j = 0; j < 4; j++)
#pragma unroll
            for (int q = 0; q < 4; q++) acc[i][j][q] = 0.f;

    const int nch = K >> 5;

    auto load_chunk = [&](int i) {
        const int s = i & 1;
        const int k0 = i << 5;
        const uint32_t st = sb + (uint32_t)s * STAGE;
#pragma unroll
        for (int c = 0; c < 2 * NC; c++) {
            const __nv_bfloat16* base = (c < NC)
                ? A + (size_t)c * sA + (size_t)bm * K + k0
                : B + (size_t)(c - NC) * sB + (size_t)bn * K + k0;
#pragma unroll
            for (int j = 0; j < 2; j++) {
                const int row = l_row0 + j * 64;
                cp16(st + (uint32_t)(c * TILEB + row * 80 + l_seg * 16),
                     base + (size_t)row * K + l_seg * 8);
            }
        }
        CP_COMMIT();
    };

    load_chunk(0);
    load_chunk(1);

    const int TA[6] = {0, 0, 1, 1, 0, 2};
    const int TB[6] = {0, 1, 0, 1, 2, 0};

    for (int i = 0; i < nch; i++) {
        CP_WAIT1();
        __syncthreads();
        const uint32_t st = sb + (uint32_t)(i & 1) * STAGE;
#pragma unroll
        for (int t = 0; t < NT; t++) {
            const uint32_t abase = st + (uint32_t)(TA[t] * TILEB) + (uint32_t)(wm * 80) + a_lo;
            const uint32_t bbase = st + (uint32_t)((NC + TB[t]) * TILEB) + (uint32_t)(wn * 80) + b_lo;
#pragma unroll
            for (int kk = 0; kk < 2; kk++) {
                uint32_t a[4][4], b[4][2];
#pragma unroll
                for (int mt = 0; mt < 4; mt++)
                    LDSM_X4(a[mt][0], a[mt][1], a[mt][2], a[mt][3],
                            abase + (uint32_t)(mt * 16 * 80 + kk * 32));
#pragma unroll
                for (int nt = 0; nt < 4; nt++)
                    LDSM_X2(b[nt][0], b[nt][1],
                            bbase + (uint32_t)(nt * 8 * 80 + kk * 32));
#pragma unroll
                for (int mt = 0; mt < 4; mt++)
#pragma unroll
                    for (int nt = 0; nt < 4; nt++)
                        mma_16816(acc[mt][nt], a[mt], b[nt]);
            }
        }
        __syncthreads();
        if (i + 2 < nch) load_chunk(i + 2);
    }

    // ---------------- epilogue ----------------
    const int r0 = lane >> 2;
    const int c0 = (lane & 3) * 2;
#pragma unroll
    for (int mt = 0; mt < 4; mt++) {
#pragma unroll
        for (int half = 0; half < 2; half++) {
            const int m = bm + wm + mt * 16 + r0 + half * 8;
#pragma unroll
            for (int nt = 0; nt < 4; nt++) {
                const int n = bn + wn + nt * 8 + c0;
                float v0 = acc[mt][nt][half * 2 + 0];
                float v1 = acc[mt][nt][half * 2 + 1];
                if (MODE == 0) {
                    const float2 bs = *reinterpret_cast<const float2*>(aux + n);
                    v0 += bs.x; v1 += bs.y;
                    *reinterpret_cast<float2*>(C + (size_t)m * D_BOT + n) = make_float2(v0, v1);
                } else if (MODE == 2) {
                    const float2 r = *reinterpret_cast<const float2*>(aux + (size_t)m * D_BOT + n);
                    v0 += r.x; v1 += r.y;
                    *reinterpret_cast<float2*>(C + (size_t)m * D_BOT + n) = make_float2(v0, v1);
                } else {
                    if (MODE == 3) { v0 *= INV_TEMP; v1 *= INV_TEMP; }
                    if (n < Nout)
                        *reinterpret_cast<float2*>(C + (size_t)m * Nout + n) = make_float2(v0, v1);
                }
            }
        }
    }
}

// ===================== split kernels =====================
template <int NCOMP>
__global__ void split_pad(const float* __restrict__ src, int src_rows, int colshift,
                          __nv_bfloat16* __restrict__ c0, __nv_bfloat16* __restrict__ c1,
                          __nv_bfloat16* __restrict__ c2, int pad_rows)
{
    const size_t total2 = ((size_t)pad_rows << colshift) >> 1;
    for (size_t i = blockIdx.x * (size_t)blockDim.x + threadIdx.x; i < total2;
         i += (size_t)gridDim.x * blockDim.x) {
        const int row = (int)((i * 2) >> colshift);
        float2 v = (row < src_rows) ? reinterpret_cast<const float2*>(src)[i]
                                    : make_float2(0.f, 0.f);
        __nv_bfloat16 h0, m0, h1, m1;
        split2f(v.x, h0, m0); split2f(v.y, h1, m1);
        __nv_bfloat162 ph; ph.x = h0; ph.y = h1;
        __nv_bfloat162 pm; pm.x = m0; pm.y = m1;
        reinterpret_cast<__nv_bfloat162*>(c0)[i] = ph;
        reinterpret_cast<__nv_bfloat162*>(c1)[i] = pm;
        if (NCOMP == 3) {
            __nv_bfloat162 pl;
            pl.x = third_comp(v.x, h0, m0);
            pl.y = third_comp(v.y, h1, m1);
            reinterpret_cast<__nv_bfloat162*>(c2)[i] = pl;
        }
    }
}

__global__ void split2_scaled(const float* __restrict__ src,
                              __nv_bfloat16* __restrict__ c0, __nv_bfloat16* __restrict__ c1)
{
    const size_t total2 = (size_t)B_ROWS * D_BOT / 2;
    for (size_t i = blockIdx.x * (size_t)blockDim.x + threadIdx.x; i < total2;
         i += (size_t)gridDim.x * blockDim.x) {
        const int row = (int)((i * 2) >> 10);
        const float sc = g_inv[row];
        float2 v = reinterpret_cast<const float2*>(src)[i];
        v.x *= sc; v.y *= sc;
        __nv_bfloat16 h0, m0, h1, m1;
        split2f(v.x, h0, m0); split2f(v.y, h1, m1);
        __nv_bfloat162 ph; ph.x = h0; ph.y = h1;
        __nv_bfloat162 pm; pm.x = m0; pm.y = m1;
        reinterpret_cast<__nv_bfloat162*>(c0)[i] = ph;
        reinterpret_cast<__nv_bfloat162*>(c1)[i] = pm;
    }
}

__global__ void transpose_split2(const float* __restrict__ src)
{
    __shared__ float tile[32][33];
    const int bx = blockIdx.x * 32;  // d
    const int by = blockIdx.y * 32;  // c
    const int x = bx + threadIdx.x;
#pragma unroll
    for (int i = 0; i < 32; i += 8) {
        const int c = by + threadIdx.y + i;
        tile[threadIdx.y + i][threadIdx.x] = (c < C_CLS) ? src[(size_t)c * D_BOT + x] : 0.f;
    }
    __syncthreads();
    const int c2 = by + threadIdx.x;
#pragma unroll
    for (int i = 0; i < 32; i += 8) {
        const int d2 = bx + threadIdx.y + i;
        const float v = tile[threadIdx.x][threadIdx.y + i];
        __nv_bfloat16 h, m;
        split2f(v, h, m);
        const size_t o = (size_t)d2 * C_PAD + c2;
        g_cTs[0][o] = h;
        g_cTs[1][o] = m;
    }
}

// ===================== masked softmax -> sm1 split2 (col-padded) =====================
__global__ void __launch_bounds__(256)
mask_softmax(const float* __restrict__ logits)
{
    const int row = blockIdx.x;
    const float* x = logits + (size_t)row * C_CLS;
    const int t = threadIdx.x;

    float v[4];
    float lmax = -INFINITY;
    int limax = C_CLS;
#pragma unroll
    for (int i = 0; i < 4; i++) {
        const int j = t + i * 256;
        const float val = (j < C_CLS) ? x[j] : -INFINITY;
        v[i] = val;
        if (val > lmax) { lmax = val; limax = j; }
    }
    __shared__ float smax[256];
    __shared__ int   simax[256];
    smax[t] = lmax; simax[t] = limax;
    __syncthreads();
#pragma unroll
    for (int s = 128; s > 0; s >>= 1) {
        if (t < s) {
            const float o = smax[t + s]; const int oi = simax[t + s];
            if (o > smax[t] || (o == smax[t] && oi < simax[t])) { smax[t] = o; simax[t] = oi; }
        }
        __syncthreads();
    }
    const int predict = simax[0];
    const float rowmax = smax[0];
    const bool priv = (predict >= SHARE);

    float e[4];
    float lsum = 0.f;
#pragma unroll
    for (int i = 0; i < 4; i++) {
        const int j = t + i * 256;
        float ee = 0.f;
        if (j < C_CLS) {
            bool mask;
            if (j == predict) mask = false;
            else if (priv)    mask = true;
            else              mask = (j < SHARE);
            ee = expf((mask ? NEG_FILL : v[i]) - rowmax);
            lsum += ee;
        }
        e[i] = ee;
    }
    __shared__ float ssum[256];
    ssum[t] = lsum;
    __syncthreads();
#pragma unroll
    for (int s = 128; s > 0; s >>= 1) {
        if (t < s) ssum[t] += ssum[t + s];
        __syncthreads();
    }
    const float inv = 1.f / ssum[0];

    __nv_bfloat16* o0 = g_sm1s[0] + (size_t)row * C_PAD;
    __nv_bfloat16* o1 = g_sm1s[1] + (size_t)row * C_PAD;
#pragma unroll
    for (int i = 0; i < 4; i++) {
        const int j = t + i * 256;
        const float p = (j < C_CLS) ? e[i] * inv : 0.f;
        __nv_bfloat16 h, m;
        split2f(p, h, m);
        o0[j] = h;
        o1[j] = m;
    }
}

// ===================== per-row inverse L2 norm =====================
__global__ void __launch_bounds__(256)
row_inv_norm(const float* __restrict__ x)
{
    const int row = blockIdx.x;
    const int t = threadIdx.x;
    const float4 v = reinterpret_cast<const float4*>(x + (size_t)row * D_BOT)[t];
    float s = v.x * v.x + v.y * v.y + v.z * v.z + v.w * v.w;
    __shared__ float sh[256];
    sh[t] = s;
    __syncthreads();
#pragma unroll
    for (int k = 128; k > 0; k >>= 1) {
        if (t < k) sh[t] += sh[t + k];
        __syncthreads();
    }
    if (t == 0) g_inv[row] = 1.f / fmaxf(sqrtf(sh[0]), EPSN);
}

// ===================== plain row softmax =====================
__global__ void __launch_bounds__(256)
softmax_rows(const float* __restrict__ in, float* __restrict__ outp)
{
    const int row = blockIdx.x;
    const float* x = in + (size_t)row * C_CLS;
    const int t = threadIdx.x;
    float v[4];
    float lmax = -INFINITY;
#pragma unroll
    for (int i = 0; i < 4; i++) {
        const int j = t + i * 256;
        v[i] = (j < C_CLS) ? x[j] : -INFINITY;
        lmax = fmaxf(lmax, v[i]);
    }
    __shared__ float sh[256];
    sh[t] = lmax;
    __syncthreads();
#pragma unroll
    for (int s = 128; s > 0; s >>= 1) {
        if (t < s) sh[t] = fmaxf(sh[t], sh[t + s]);
        __syncthreads();
    }
    const float rowmax = sh[0];
    __syncthreads();
    float e[4];
    float lsum = 0.f;
#pragma unroll
    for (int i = 0; i < 4; i++) {
        const int j = t + i * 256;
        float ee = 0.f;
        if (j < C_CLS) { ee = expf(v[i] - rowmax); lsum += ee; }
        e[i] = ee;
    }
    sh[t] = lsum;
    __syncthreads();
#pragma unroll
    for (int s = 128; s > 0; s >>= 1) {
        if (t < s) sh[t] += sh[t + s];
        __syncthreads();
    }
    const float inv = 1.f / sh[0];
    float* o = outp + (size_t)row * C_CLS;
#pragma unroll
    for (int i = 0; i < 4; i++) {
        const int j = t + i * 256;
        if (j < C_CLS) o[j] = e[i] * inv;
    }
}

// =====================================================================
extern "C" void kernel_launch(void* const* d_in, const int* in_sizes, int n_in,
                              void* d_out, int out_size)
{
    const float* features = (const float*)d_in[0];
    const float* W_b      = (const float*)d_in[1];
    const float* b_b      = (const float*)d_in[2];
    const float* W1       = (const float*)d_in[3];
    const float* W2       = (const float*)d_in[4];
    const float* centroid = (const float*)d_in[5];

    float* out = (float*)d_out;
    float* feats        = out;
    float* features_aug = feats + (size_t)B_ROWS * D_BOT;
    float* outputs1     = features_aug + (size_t)B_ROWS * D_BOT;
    float* outputs2     = outputs1 + (size_t)B_ROWS * C_CLS;
    float* softmax_out  = outputs2 + (size_t)B_ROWS * C_CLS;

    __nv_bfloat16 *feat3, *Wb3, *feats3, *W1s, *sm1s, *cTs, *faug2, *W2s;
    cudaGetSymbolAddress((void**)&feat3,  g_feat3);
    cudaGetSymbolAddress((void**)&Wb3,    g_Wb3);
    cudaGetSymbolAddress((void**)&feats3, g_feats3);
    cudaGetSymbolAddress((void**)&W1s,    g_W1s);
    cudaGetSymbolAddress((void**)&sm1s,   g_sm1s);
    cudaGetSymbolAddress((void**)&cTs,    g_cTs);
    cudaGetSymbolAddress((void**)&faug2,  g_faug2);
    cudaGetSymbolAddress((void**)&W2s,    g_W2s);

    const size_t S_feat  = (size_t)B_ROWS * D_INF;
    const size_t S_Wb    = (size_t)D_BOT  * D_INF;
    const size_t S_feats = (size_t)B_ROWS * D_BOT;
    const size_t S_W1    = (size_t)C_PAD  * D_BOT;
    const size_t S_sm1   = (size_t)B_ROWS * C_PAD;
    const size_t S_cT    = (size_t)D_BOT  * C_PAD;

    constexpr int TILEB = 128 * 80;
    constexpr int SMEM3 = 2 * (2 * 3 * TILEB);   // 122880
    constexpr int SMEM2 = 2 * (2 * 2 * TILEB);   // 81920
    cudaFuncSetAttribute(gemm_mma<3, 0>, cudaFuncAttributeMaxDynamicSharedMemorySize, SMEM3);
    cudaFuncSetAttribute(gemm_mma<3, 1>, cudaFuncAttributeMaxDynamicSharedMemorySize, SMEM3);
    cudaFuncSetAttribute(gemm_mma<2, 2>, cudaFuncAttributeMaxDynamicSharedMemorySize, SMEM2);
    cudaFuncSetAttribute(gemm_mma<2, 3>, cudaFuncAttributeMaxDynamicSharedMemorySize, SMEM2);

    const dim3 blk(256);
    const dim3 grid8(8, 64);

    // splits for GEMM1
    split_pad<3><<<1024, blk>>>(features, B_ROWS, 11, feat3, feat3 + S_feat, feat3 + 2 * S_feat, B_ROWS);
    split_pad<3><<<512,  blk>>>(W_b, D_BOT, 11, Wb3, Wb3 + S_Wb, Wb3 + 2 * S_Wb, D_BOT);

    // GEMM1: feats = features @ W_b^T + b_b
    gemm_mma<3, 0><<<grid8, blk, SMEM3>>>(feat3, S_feat, Wb3, S_Wb, feats, D_INF, D_BOT, b_b);

    // splits for GEMM2
    split_pad<3><<<1024, blk>>>(feats, B_ROWS, 10, feats3, feats3 + S_feats, feats3 + 2 * S_feats, B_ROWS);
    split_pad<3><<<512,  blk>>>(W1, C_CLS, 10, W1s, W1s + S_W1, W1s + 2 * S_W1, C_PAD);

    // GEMM2: outputs1 = feats @ W1^T
    gemm_mma<3, 1><<<grid8, blk, SMEM3>>>(feats3, S_feats, W1s, S_W1, outputs1, D_BOT, C_CLS, nullptr);

    // centroid^T split2 + masked softmax
    transpose_split2<<<dim3(D_BOT / 32, C_PAD / 32), dim3(32, 8)>>>(centroid);
    mask_softmax<<<B_ROWS, blk>>>(outputs1);

    // GEMM3: features_aug = sm1 @ centroid + feats
    gemm_mma<2, 2><<<grid8, blk, SMEM2>>>(sm1s, S_sm1, cTs, S_cT, features_aug, C_PAD, D_BOT, feats);

    // normalize, fold 1/||row|| into A split
    row_inv_norm<<<B_ROWS, blk>>>(features_aug);
    split2_scaled<<<1024, blk>>>(features_aug, faug2, faug2 + S_feats);
    split_pad<2><<<512, blk>>>(W2, C_CLS, 10, W2s, W2s + S_W1, nullptr, C_PAD);

    // GEMM4: outputs2 = x @ W2^T / TEMP
    gemm_mma<2, 3><<<grid8, blk, SMEM2>>>(faug2, S_feats, W2s, S_W1, outputs2, D_BOT, C_CLS, nullptr);

    softmax_rows<<<B_ROWS, blk>>>(outputs2, softmax_out);
}